// round 3
// baseline (speedup 1.0000x reference)
#include <cuda_runtime.h>
#include <cstdint>

// Fixed problem shape: x [B=32, T=4096, N=256] float32 -> z same shape.
#define BB 32
#define TT 4096
#define NN 256
#define BN (BB * NN)          // 8192 chains, power of two (2^13)
#define LOG2_BN 13
#define CHUNK 64              // time steps per chunk
#define NC (TT / CHUNK)       // 64 chunks
#define REFR 5                // refractory period

// Static scratch (allocation-free rule): ~6.5 MB total.
__device__ uint64_t g_mask[NC][BN];   // sign bitmask per (chunk, chain)   4 MB
__device__ uint32_t g_map[NC][BN];    // 6x3-bit transition map            2 MB
__device__ uint8_t  g_qin[NC][BN];    // incoming q per (chunk, chain)   0.5 MB

// Greedy spike simulation on a 64-bit positivity mask, starting eligible at
// 'start' (equivalent to incoming q == start). Returns q after the last step.
// Spike at first set bit >= pos; next eligible pos = spike + REFR + 1.
__device__ __forceinline__ int sim_final_q(uint64_t mask, int start) {
    int pos = start;
    int last = -64;  // sentinel: "no spike"
    while (pos < CHUNK) {
        uint64_t m = mask >> pos;
        if (!m) break;
        int s = pos + __ffsll((long long)m) - 1;
        last = s;
        pos = s + REFR + 1;
    }
    int q = last + REFR - (CHUNK - 1);   // max(0, 5 - (63 - last))
    return q > 0 ? q : 0;
}

// Pass 1: per (chain, chunk) — read x chunk, emit sign bitmask + transition map.
__global__ void __launch_bounds__(256) pass1_mask_map(const float* __restrict__ x) {
    int tid = blockIdx.x * blockDim.x + threadIdx.x;   // 0 .. BN*NC-1
    int bn = tid & (BN - 1);
    int c  = tid >> LOG2_BN;
    int b  = bn >> 8;          // / NN
    int n  = bn & (NN - 1);

    const float* px = x + ((size_t)b * TT + (size_t)c * CHUNK) * NN + n;

    uint64_t mask = 0;
#pragma unroll 16
    for (int i = 0; i < CHUNK; ++i) {
        float v = px[(size_t)i * NN];   // coalesced: 32 consecutive n per warp
        mask |= (uint64_t)(v > 0.0f) << i;
    }
    g_mask[c][bn] = mask;

    uint32_t map = 0;
#pragma unroll
    for (int k = 0; k <= REFR; ++k)
        map |= (uint32_t)sim_final_q(mask, k) << (3 * k);
    g_map[c][bn] = map;
}

// Pass 2: per chain — sequentially compose the 64 chunk maps.
__global__ void __launch_bounds__(256) pass2_compose() {
    int bn = blockIdx.x * blockDim.x + threadIdx.x;    // 0 .. BN-1
    int q = 0;
    for (int base = 0; base < NC; base += 8) {
        uint32_t m[8];
#pragma unroll
        for (int j = 0; j < 8; ++j) m[j] = g_map[base + j][bn];  // batched loads
#pragma unroll
        for (int j = 0; j < 8; ++j) {
            g_qin[base + j][bn] = (uint8_t)q;
            q = (m[j] >> (3 * q)) & 7;                 // only ALU-dependent
        }
    }
}

// Pass 3: per (chain, chunk) — rebuild spike mask with known incoming q, write z.
__global__ void __launch_bounds__(256) pass3_emit(float* __restrict__ out) {
    int tid = blockIdx.x * blockDim.x + threadIdx.x;
    int bn = tid & (BN - 1);
    int c  = tid >> LOG2_BN;

    uint64_t mask = g_mask[c][bn];
    int pos = g_qin[c][bn];

    uint64_t spikes = 0;
    while (pos < CHUNK) {
        uint64_t m = mask >> pos;
        if (!m) break;
        int s = pos + __ffsll((long long)m) - 1;
        spikes |= 1ull << s;
        pos = s + REFR + 1;
    }

    int b = bn >> 8;
    int n = bn & (NN - 1);
    float* po = out + ((size_t)b * TT + (size_t)c * CHUNK) * NN + n;
#pragma unroll 16
    for (int i = 0; i < CHUNK; ++i) {
        uint32_t bit = (uint32_t)(spikes >> i) & 1u;
        po[(size_t)i * NN] = (float)bit;               // coalesced 128B stores
    }
}

extern "C" void kernel_launch(void* const* d_in, const int* in_sizes, int n_in,
                              void* d_out, int out_size) {
    (void)in_sizes; (void)n_in; (void)out_size;
    const float* x = (const float*)d_in[0];
    float* out = (float*)d_out;

    const int threads = 256;
    const int grid_big = (BN * NC) / threads;   // 2048 blocks
    const int grid_small = BN / threads;        // 32 blocks

    pass1_mask_map<<<grid_big, threads>>>(x);
    pass2_compose<<<grid_small, threads>>>();
    pass3_emit<<<grid_big, threads>>>(out);
}